// round 9
// baseline (speedup 1.0000x reference)
#include <cuda_runtime.h>
#include <math.h>

#ifndef M_PI
#define M_PI 3.14159265358979323846
#endif

#define NBLK  148
#define NT    448
#define NWARP 14
#define TXDIM 421
#define TYDIM 421
#define NRMAX 3
#define SRCI  210
#define SRCJ  210
#define RSLOT 4
#define SRCBUF 512

// Global flag+data packets (unchanged mechanism from round 4/6):
//  pktT: {ez_row_first, 0, _, seq} — consumed by bid-1 as ezBot
//  pktB: {ez_row_last, hy_row_last, _, seq} — consumed by bid+1 as ezTop/hyTop
__device__ float4   g_pktT[RSLOT][NBLK][NT];
__device__ float4   g_pktB[RSLOT][NBLK][NT];
__device__ unsigned g_epoch;   // monotonic across graph replays

static __device__ __forceinline__ void st_pkt(float4* p, float x, float y, unsigned seq) {
    asm volatile("st.volatile.global.v4.f32 [%0], {%1,%2,%3,%4};"
                 :: "l"(p), "f"(x), "f"(y), "f"(0.f), "f"(__uint_as_float(seq)) : "memory");
}
static __device__ __forceinline__ float4 ld_pkt(const float4* p) {
    float4 v;
    asm volatile("ld.volatile.global.v4.f32 {%0,%1,%2,%3}, [%4];"
                 : "=f"(v.x), "=f"(v.y), "=f"(v.z), "=f"(v.w) : "l"(p) : "memory");
    return v;
}
// SMEM 16B volatile (single STS.128/LDS.128 -> tear-free packet)
static __device__ __forceinline__ void sts_v4(float4* p, float x, float y, float z, unsigned seq) {
    unsigned a = (unsigned)__cvta_generic_to_shared(p);
    asm volatile("st.volatile.shared.v4.f32 [%0], {%1,%2,%3,%4};"
                 :: "r"(a), "f"(x), "f"(y), "f"(z), "f"(__uint_as_float(seq)) : "memory");
}
static __device__ __forceinline__ float4 lds_v4(const float4* p) {
    unsigned a = (unsigned)__cvta_generic_to_shared((void*)p);
    float4 v;
    asm volatile("ld.volatile.shared.v4.f32 {%0,%1,%2,%3}, [%4];"
                 : "=f"(v.x), "=f"(v.y), "=f"(v.z), "=f"(v.w) : "r"(a) : "memory");
    return v;
}

__global__ void __launch_bounds__(NT, 1)
fdtd_mlor_kernel(const float* __restrict__ src, int src_len,
                 const float* __restrict__ C1a, const float* __restrict__ C2a,
                 const float* __restrict__ Cbdxa, const float* __restrict__ Cbdya,
                 const float* __restrict__ dbhxa, const float* __restrict__ dbhya,
                 const float* __restrict__ Caa, const float* __restrict__ Cba,
                 const float* __restrict__ Cca, const float* __restrict__ Cda,
                 const float* __restrict__ Cea,
                 const float* __restrict__ sig_ex, const float* __restrict__ sig_ey,
                 const float* __restrict__ sig_hx, const float* __restrict__ sig_hy,
                 const int* __restrict__ nsp,
                 float* __restrict__ out,
                 float kE, float kMu)
{
    const int bid  = blockIdx.x;
    const int j    = threadIdx.x;
    const int w    = j >> 5;
    const int lane = j & 31;

    const float ca   = Caa[0], cb = Cba[0], cc = Cca[0], cd = Cda[0], ce = Cea[0];
    const float C1   = C1a[0], C2 = C2a[0];
    const float Cbdx = Cbdxa[0], Cbdy = Cbdya[0];
    const float dbhx = dbhxa[0], dbhy = dbhya[0];

    int n = nsp ? nsp[0] : 200;
    if (n > src_len) n = src_len;
    if (n < 0) n = 0;

    const int r0 = (bid * TXDIM) / NBLK;
    const int r1 = ((bid + 1) * TXDIM) / NBLK;
    const int nrows = r1 - r0;                 // 2 or 3

    const bool colE = (j < TYDIM);
    const bool colH = (j < TYDIM - 1);
    const bool colM = (j >= 1 && j < TYDIM);
    const bool inJ  = (j >= 1 && j <= TYDIM - 2);

    float cEyE = 1.f, cEyMu = 1.f, cHyMu = 1.f, cHyMuM = 1.f;
    if (colE) { float s = sig_ey[j]; cEyE = expf(-s * kE); cEyMu = expf(-s * kMu); }
    if (colH) cHyMu  = expf(-sig_hy[j]     * kMu);
    if (colM) cHyMuM = expf(-sig_hy[j - 1] * kMu);

    float fDe[NRMAX], fHx[NRMAX], fHxm[NRMAX], fHy[NRMAX];
    bool  inI[NRMAX];
    #pragma unroll
    for (int r = 0; r < NRMAX; ++r) {
        fDe[r] = 0.f; fHx[r] = 0.f; fHxm[r] = 0.f; fHy[r] = 0.f; inI[r] = false;
        if (r < nrows) {
            int i = r0 + r;
            float sx  = sig_ex[i];
            float rMu = expf(-sx * kMu);
            fDe[r]  = expf(-sx * kE) * cEyE;
            fHx[r]  = rMu * cHyMu;
            fHxm[r] = rMu * cHyMuM;
            fHy[r]  = (i < TXDIM - 1) ? expf(-sig_hx[i] * kMu) * cEyMu : 0.f;
            inI[r]  = (i >= 1 && i <= TXDIM - 2);
        }
    }
    const float fHyHalo = (r0 > 0) ? expf(-sig_hx[r0 - 1] * kMu) * cEyMu : 0.f;

    // Field state — registers for the entire run
    float ez[NRMAX]   = {0.f, 0.f, 0.f};
    float eold[NRMAX] = {0.f, 0.f, 0.f};
    float jz[NRMAX]   = {0.f, 0.f, 0.f};
    float jold[NRMAX] = {0.f, 0.f, 0.f};
    float hx[NRMAX]   = {0.f, 0.f, 0.f};   // Hx(i, j)
    float hxm[NRMAX]  = {0.f, 0.f, 0.f};   // Hx(i, j-1)
    float hy[NRMAX]   = {0.f, 0.f, 0.f};

    // Warp-edge packets: [slot][warp][side]  side0 = warp's lane0 ez rows, side1 = lane31
    __shared__ float4 sEdge[2][NWARP][2];
    __shared__ float  sSrc[SRCBUF];

    if (j < 2 * NWARP * 2) ((float4*)sEdge)[j] = make_float4(0.f, 0.f, 0.f, 0.f); // seq=0
    if (j < n && j < SRCBUF) sSrc[j] = src[j];

    const unsigned base = *(volatile unsigned*)&g_epoch;

    __syncthreads();   // the ONLY block-wide barrier: init visible

#define EUPD(r, hyBelow, srcv)                                                     \
    do {                                                                           \
        float eznew_ = 0.f;                                                        \
        if (inI[(r)] && inJ) {                                                     \
            float chy_ = hy[(r)] - (hyBelow);                                      \
            float chx_ = hx[(r)] - hxm[(r)];                                       \
            eznew_ = fDe[(r)] * (C1 * ez[(r)] + Cbdx * chy_ - Cbdy * chx_          \
                                 - C2 * phi[(r)]);                                 \
            if (r0 + (r) == SRCI && j == SRCJ) eznew_ += (srcv);                   \
        }                                                                          \
        jold[(r)] = jz[(r)]; jz[(r)] = jpart[(r)] + cc * eznew_;                   \
        eold[(r)] = ez[(r)]; ez[(r)] = eznew_;                                     \
    } while (0)

    for (int t = 0; t < n; ++t) {
        const int slot  = t & 1;          // read slot for warp-edge packets
        const int slotW = slot ^ 1;       // write slot
        const int spG   = (t + RSLOT - 1) & (RSLOT - 1);
        const unsigned wantG = base + (unsigned)t;
        const unsigned wantW = (unsigned)t;
        const float sv = (t < SRCBUF) ? sSrc[t] : 0.f;

        // ---- Optimistic global polls (RT hides under local work) ----
        const bool needB = (t > 0) && (bid > 0)        && colE;
        const bool needT = (t > 0) && (bid < NBLK - 1) && colE;
        const float4* pB = &g_pktB[spG][bid - 1][j];
        const float4* pT = &g_pktT[spG][bid + 1][j];
        float4 vB = make_float4(0.f, 0.f, 0.f, 0.f);
        float4 vT = make_float4(0.f, 0.f, 0.f, 0.f);
        if (needB) vB = ld_pkt(pB);
        if (needT) vT = ld_pkt(pT);

        // ---- J/E polynomial precompute (state t) ----
        float phi[NRMAX], jpart[NRMAX];
        #pragma unroll
        for (int r = 0; r < NRMAX; ++r) {
            float jp = ca * jz[r] + cb * jold[r] + cd * ez[r] + ce * eold[r];
            jpart[r] = jp;
            phi[r]   = jp + jz[r];
        }

        // ---- Warp-edge SMEM polls (lanes 0 / 31 only; ~30 cyc) ----
        float eL0 = 0.f, eL1 = 0.f, eL2 = 0.f;
        float eR0 = 0.f, eR1 = 0.f, eR2 = 0.f;
        if (lane == 0 && w > 0) {
            const float4* e = &sEdge[slot][w - 1][1];
            float4 v = lds_v4(e);
            while (__float_as_uint(v.w) < wantW) v = lds_v4(e);
            eL0 = v.x; eL1 = v.y; eL2 = v.z;
        }
        if (lane == 31 && w < NWARP - 1) {
            const float4* e = &sEdge[slot][w + 1][0];
            float4 v = lds_v4(e);
            while (__float_as_uint(v.w) < wantW) v = lds_v4(e);
            eR0 = v.x; eR1 = v.y; eR2 = v.z;
        }

        // ---- j±1 exchange: shfl in-warp, SMEM packets at warp edges ----
        float ezp1[NRMAX], ezm1[NRMAX];
        #pragma unroll
        for (int r = 0; r < NRMAX; ++r) {
            ezp1[r] = __shfl_down_sync(0xffffffffu, ez[r], 1);
            ezm1[r] = __shfl_up_sync  (0xffffffffu, ez[r], 1);
        }
        if (lane == 31) { ezp1[0] = eR0; ezp1[1] = eR1; ezp1[2] = eR2; }
        if (lane == 0)  { ezm1[0] = eL0; ezm1[1] = eL1; ezm1[2] = eL2; }

        // ---- Local H updates ----
        #pragma unroll
        for (int r = 0; r < NRMAX; ++r) {
            if (r < nrows) {
                if (colH) hx[r]  = fHx[r]  * (hx[r]  - dbhx * (ezp1[r] - ez[r]));
                if (colM) hxm[r] = fHxm[r] * (hxm[r] - dbhx * (ez[r] - ezm1[r]));
                if (r + 1 < nrows) hy[r] = fHy[r] * (hy[r] + dbhy * (ez[r + 1] - ez[r]));
            }
        }

        // ---- Complete global polls ----
        float ezTop = 0.f, hyTop = 0.f, ezBot = 0.f;
        if (needB) {
            while (__float_as_uint(vB.w) < wantG) vB = ld_pkt(pB);
            ezTop = vB.x; hyTop = vB.y;
        }
        if (needT) {
            while (__float_as_uint(vT.w) < wantG) vT = ld_pkt(pT);
            ezBot = vT.x;
        }

        // ---- Boundary H ----
        float hyPrev = 0.f;
        if (colE) {
            if (nrows == 3) hy[2] = fHy[2] * (hy[2] + dbhy * (ezBot - ez[2]));
            else            hy[1] = fHy[1] * (hy[1] + dbhy * (ezBot - ez[1]));
            if (bid > 0)
                hyPrev = fHyHalo * (hyTop + dbhy * (ez[0] - ezTop));
        }

        // ---- E + J update; publish global packets ASAP ----
        const int sG = t & (RSLOT - 1);
        const unsigned seqG = base + (unsigned)t + 1u;
        if (colE) {
            EUPD(0, hyPrev, sv);
            st_pkt(&g_pktT[sG][bid][j], ez[0], 0.f, seqG);
            if (nrows == 3) {
                EUPD(2, hy[1], sv);
                st_pkt(&g_pktB[sG][bid][j], ez[2], hy[2], seqG);
                EUPD(1, hy[0], sv);
            } else {
                EUPD(1, hy[0], sv);
                st_pkt(&g_pktB[sG][bid][j], ez[1], hy[1], seqG);
            }
        }

        // ---- Publish warp-edge packets (all ez rows now at t+1) ----
        if (lane == 0)
            sts_v4(&sEdge[slotW][w][0], ez[0], ez[1], ez[2], (unsigned)(t + 1));
        if (lane == 31)
            sts_v4(&sEdge[slotW][w][1], ez[0], ez[1], ez[2], (unsigned)(t + 1));
        // NO __syncthreads — warps free-run with bounded skew
    }
#undef EUPD

    #pragma unroll
    for (int r = 0; r < NRMAX; ++r) {
        if (r < nrows && colE) out[(r0 + r) * TYDIM + j] = ez[r];
    }

    // Advance epoch for the next graph replay (same value from every block)
    if (j == 0) *(volatile unsigned*)&g_epoch = base + (unsigned)n;
}

extern "C" void kernel_launch(void* const* d_in, const int* in_sizes, int n_in,
                              void* d_out, int out_size) {
    const float* src    = (const float*)d_in[0];
    const float* C1a    = (const float*)d_in[1];
    const float* C2a    = (const float*)d_in[2];
    const float* Cbdxa  = (const float*)d_in[3];
    const float* Cbdya  = (const float*)d_in[4];
    const float* dbhxa  = (const float*)d_in[5];
    const float* dbhya  = (const float*)d_in[6];
    const float* Caa    = (const float*)d_in[7];
    const float* Cba    = (const float*)d_in[8];
    const float* Cca    = (const float*)d_in[9];
    const float* Cda    = (const float*)d_in[10];
    const float* Cea    = (const float*)d_in[11];
    const float* sigex  = (const float*)d_in[12];
    const float* sigey  = (const float*)d_in[13];
    const float* sighx  = (const float*)d_in[14];
    const float* sighy  = (const float*)d_in[15];
    const int*   nsp    = (n_in >= 17) ? (const int*)d_in[16] : nullptr;

    const double EPS0 = 1e-9 / 36.0 / M_PI;
    const double MU0  = 4.0 * M_PI * 1e-7;
    const double C0   = 1.0 / sqrt(MU0 * EPS0);
    const double DX = 2.5e-8, DY = 2.5e-8;
    const double DT = 0.99 / C0 / sqrt(1.0 / (DX * DX) + 1.0 / (DY * DY));
    const float kE  = (float)(DT / EPS0);
    const float kMu = (float)(DT / MU0);

    fdtd_mlor_kernel<<<NBLK, NT>>>(src, in_sizes[0],
                                   C1a, C2a, Cbdxa, Cbdya, dbhxa, dbhya,
                                   Caa, Cba, Cca, Cda, Cea,
                                   sigex, sigey, sighx, sighy,
                                   nsp, (float*)d_out, kE, kMu);
    (void)out_size;
}

// round 10
// speedup vs baseline: 2.0805x; 2.0805x over previous
#include <cuda_runtime.h>
#include <math.h>

#ifndef M_PI
#define M_PI 3.14159265358979323846
#endif

#define NBLK  148
#define NT    224          // 7 warps; each thread owns columns 2k, 2k+1
#define NWARP 7
#define NCOLS 448
#define TXDIM 421
#define TYDIM 421
#define NRMAX 3
#define SRCI  210
#define SRCJ  210
#define RSLOT 4
#define SRCBUF 256

// Flag+data packets (flag rides with data in one 16B sector), per COLUMN:
//  pktT: {ez_row_first, 0, _, seq} — consumed by bid-1 as ezBot
//  pktB: {ez_row_last, hy_row_last, _, seq} — consumed by bid+1 as ezTop/hyTop
__device__ float4   g_pktT[RSLOT][NBLK][NCOLS];
__device__ float4   g_pktB[RSLOT][NBLK][NCOLS];
__device__ unsigned g_epoch;   // monotonic across graph replays

static __device__ __forceinline__ void st_pkt(float4* p, float x, float y, unsigned seq) {
    asm volatile("st.volatile.global.v4.f32 [%0], {%1,%2,%3,%4};"
                 :: "l"(p), "f"(x), "f"(y), "f"(0.f), "f"(__uint_as_float(seq)) : "memory");
}
static __device__ __forceinline__ float4 ld_pkt(const float4* p) {
    float4 v;
    asm volatile("ld.volatile.global.v4.f32 {%0,%1,%2,%3}, [%4];"
                 : "=f"(v.x), "=f"(v.y), "=f"(v.z), "=f"(v.w) : "l"(p) : "memory");
    return v;
}

__global__ void __launch_bounds__(NT, 1)
fdtd_mlor_kernel(const float* __restrict__ src, int src_len,
                 const float* __restrict__ C1a, const float* __restrict__ C2a,
                 const float* __restrict__ Cbdxa, const float* __restrict__ Cbdya,
                 const float* __restrict__ dbhxa, const float* __restrict__ dbhya,
                 const float* __restrict__ Caa, const float* __restrict__ Cba,
                 const float* __restrict__ Cca, const float* __restrict__ Cda,
                 const float* __restrict__ Cea,
                 const float* __restrict__ sig_ex, const float* __restrict__ sig_ey,
                 const float* __restrict__ sig_hx, const float* __restrict__ sig_hy,
                 const int* __restrict__ nsp,
                 float* __restrict__ out,
                 float kE, float kMu)
{
    const int bid  = blockIdx.x;
    const int k    = threadIdx.x;
    const int w    = k >> 5;
    const int lane = k & 31;
    const int c0   = 2 * k;        // even column
    const int c1   = c0 + 1;       // odd column

    const float ca   = Caa[0], cb = Cba[0], cc = Cca[0], cd = Cda[0], ce = Cea[0];
    const float C1   = C1a[0], C2 = C2a[0];
    const float Cbdx = Cbdxa[0], Cbdy = Cbdya[0];
    const float dbhx = dbhxa[0], dbhy = dbhya[0];

    int n = nsp ? nsp[0] : 200;
    if (n > src_len) n = src_len;
    if (n < 0) n = 0;

    const int r0 = (bid * TXDIM) / NBLK;
    const int r1 = ((bid + 1) * TXDIM) / NBLK;
    const int nrows = r1 - r0;                 // 2 or 3

    // Per-column predicates (index 0 -> c0, 1 -> c1)
    const int  col[2]  = {c0, c1};
    bool colE[2], colH[2], colM[2], inJ[2];
    #pragma unroll
    for (int c = 0; c < 2; ++c) {
        colE[c] = (col[c] < TYDIM);
        colH[c] = (col[c] < TYDIM - 1);
        colM[c] = (col[c] >= 1 && col[c] < TYDIM);
        inJ[c]  = (col[c] >= 1 && col[c] <= TYDIM - 2);
    }

    // Column decay factors
    float cEyE[2], cEyMu[2], cHyMu[2], cHyMuM[2];
    #pragma unroll
    for (int c = 0; c < 2; ++c) {
        cEyE[c] = 1.f; cEyMu[c] = 1.f; cHyMu[c] = 1.f; cHyMuM[c] = 1.f;
        if (colE[c]) { float s = sig_ey[col[c]]; cEyE[c] = expf(-s * kE); cEyMu[c] = expf(-s * kMu); }
        if (colH[c]) cHyMu[c]  = expf(-sig_hy[col[c]]     * kMu);
        if (colM[c]) cHyMuM[c] = expf(-sig_hy[col[c] - 1] * kMu);
    }

    float fDe[2][NRMAX], fHx[2][NRMAX], fHxm[2][NRMAX], fHy[2][NRMAX];
    bool  inI[NRMAX];
    #pragma unroll
    for (int r = 0; r < NRMAX; ++r) {
        inI[r] = false;
        float rE = 0.f, rMu = 0.f, rHy = 0.f;
        if (r < nrows) {
            int i = r0 + r;
            float sx = sig_ex[i];
            rE  = expf(-sx * kE);
            rMu = expf(-sx * kMu);
            rHy = (i < TXDIM - 1) ? expf(-sig_hx[i] * kMu) : 0.f;
            inI[r] = (i >= 1 && i <= TXDIM - 2);
        }
        #pragma unroll
        for (int c = 0; c < 2; ++c) {
            fDe[c][r]  = rE  * cEyE[c];
            fHx[c][r]  = rMu * cHyMu[c];
            fHxm[c][r] = rMu * cHyMuM[c];
            fHy[c][r]  = rHy * cEyMu[c];
        }
    }
    float fHyHalo[2] = {0.f, 0.f};
    if (r0 > 0) {
        float rh = expf(-sig_hx[r0 - 1] * kMu);
        fHyHalo[0] = rh * cEyMu[0];
        fHyHalo[1] = rh * cEyMu[1];
    }

    // Field state — registers for the whole run: [col][row]
    float ez[2][NRMAX]   = {{0.f,0.f,0.f},{0.f,0.f,0.f}};
    float eold[2][NRMAX] = {{0.f,0.f,0.f},{0.f,0.f,0.f}};
    float jz[2][NRMAX]   = {{0.f,0.f,0.f},{0.f,0.f,0.f}};
    float jold[2][NRMAX] = {{0.f,0.f,0.f},{0.f,0.f,0.f}};
    float hx[2][NRMAX]   = {{0.f,0.f,0.f},{0.f,0.f,0.f}};  // Hx(i, col)
    float hxm[2][NRMAX]  = {{0.f,0.f,0.f},{0.f,0.f,0.f}};  // Hx(i, col-1)
    float hy[2][NRMAX]   = {{0.f,0.f,0.f},{0.f,0.f,0.f}};

    // Warp-edge Ez (double-buffered; read AFTER barrier — never spun on)
    // sEdgeL[s][w][r] = warp w, lane0's c0 ez ; sEdgeR[s][w][r] = lane31's c1 ez
    __shared__ float sEdgeL[2][NWARP][NRMAX];
    __shared__ float sEdgeR[2][NWARP][NRMAX];
    __shared__ float sSrc[SRCBUF];

    if (k < 2 * NWARP * NRMAX) {
        ((float*)sEdgeL)[k] = 0.f;
        ((float*)sEdgeR)[k] = 0.f;
    }
    if (k < n && k < SRCBUF) sSrc[k] = src[k];

    const unsigned base = *(volatile unsigned*)&g_epoch;

    __syncthreads();   // init visible

#define EUPD(c, r, hyBelow, srcadd)                                                \
    do {                                                                           \
        float eznew_ = 0.f;                                                        \
        if (inI[(r)] && inJ[(c)]) {                                                \
            float chy_ = hy[(c)][(r)] - (hyBelow);                                 \
            float chx_ = hx[(c)][(r)] - hxm[(c)][(r)];                             \
            eznew_ = fDe[(c)][(r)] * (C1 * ez[(c)][(r)] + Cbdx * chy_              \
                                      - Cbdy * chx_ - C2 * phi[(c)][(r)]);         \
            if (srcadd) eznew_ += sv;                                              \
        }                                                                          \
        jold[(c)][(r)] = jz[(c)][(r)];                                             \
        jz[(c)][(r)]   = jpart[(c)][(r)] + cc * eznew_;                            \
        eold[(c)][(r)] = ez[(c)][(r)];                                             \
        ez[(c)][(r)]   = eznew_;                                                   \
    } while (0)

    const bool srcHere0 = (col[0] == SRCJ);   // SRCJ is even -> only c0 can match

    for (int t = 0; t < n; ++t) {
        const int slot  = t & 1;
        const int slotW = slot ^ 1;
        const int spG   = (t + RSLOT - 1) & (RSLOT - 1);
        const unsigned wantG = base + (unsigned)t;
        const float sv = (t < SRCBUF) ? sSrc[t] : src[t];

        // ---- Optimistic global polls (both columns, both directions) ----
        const bool needB = (t > 0) && (bid > 0);
        const bool needT = (t > 0) && (bid < NBLK - 1);
        float4 vB[2], vT[2];
        const float4 *pB[2], *pT[2];
        #pragma unroll
        for (int c = 0; c < 2; ++c) {
            vB[c] = make_float4(0.f, 0.f, 0.f, 0.f);
            vT[c] = make_float4(0.f, 0.f, 0.f, 0.f);
            pB[c] = &g_pktB[spG][bid - 1][col[c]];
            pT[c] = &g_pktT[spG][bid + 1][col[c]];
            if (needB && colE[c]) vB[c] = ld_pkt(pB[c]);
            if (needT && colE[c]) vT[c] = ld_pkt(pT[c]);
        }

        // ---- J/E polynomial precompute (state t) — overlaps poll RT ----
        float phi[2][NRMAX], jpart[2][NRMAX];
        #pragma unroll
        for (int c = 0; c < 2; ++c) {
            #pragma unroll
            for (int r = 0; r < NRMAX; ++r) {
                float jp = ca * jz[c][r] + cb * jold[c][r] + cd * ez[c][r] + ce * eold[c][r];
                jpart[c][r] = jp;
                phi[c][r]   = jp + jz[c][r];
            }
        }

        // ---- Warp-edge Ez reads (barrier-protected, never stale) ----
        float ezLm1[NRMAX], ezRp1[NRMAX];   // Ez(c0-1), Ez(c1+1) for edge lanes
        #pragma unroll
        for (int r = 0; r < NRMAX; ++r) { ezLm1[r] = 0.f; ezRp1[r] = 0.f; }
        if (lane == 0 && w > 0) {
            #pragma unroll
            for (int r = 0; r < NRMAX; ++r) ezLm1[r] = sEdgeR[slot][w - 1][r];
        }
        if (lane == 31 && w < NWARP - 1) {
            #pragma unroll
            for (int r = 0; r < NRMAX; ++r) ezRp1[r] = sEdgeL[slot][w + 1][r];
        }

        // ---- Cross-thread j halo via shfl ----
        float ezp1c1[NRMAX], ezm1c0[NRMAX];
        #pragma unroll
        for (int r = 0; r < NRMAX; ++r) {
            float dn = __shfl_down_sync(0xffffffffu, ez[0][r], 1);  // next thread's c0
            float up = __shfl_up_sync  (0xffffffffu, ez[1][r], 1);  // prev thread's c1
            ezp1c1[r] = (lane == 31) ? ezRp1[r] : dn;
            ezm1c0[r] = (lane == 0)  ? ezLm1[r] : up;
        }

        // ---- Local H updates (both columns; independent chains) ----
        #pragma unroll
        for (int r = 0; r < NRMAX; ++r) {
            if (r < nrows) {
                if (colH[0]) hx[0][r]  = fHx[0][r]  * (hx[0][r]  - dbhx * (ez[1][r]  - ez[0][r]));
                if (colH[1]) hx[1][r]  = fHx[1][r]  * (hx[1][r]  - dbhx * (ezp1c1[r] - ez[1][r]));
                if (colM[0]) hxm[0][r] = fHxm[0][r] * (hxm[0][r] - dbhx * (ez[0][r] - ezm1c0[r]));
                if (colM[1]) hxm[1][r] = fHxm[1][r] * (hxm[1][r] - dbhx * (ez[1][r] - ez[0][r]));
                if (r + 1 < nrows) {
                    hy[0][r] = fHy[0][r] * (hy[0][r] + dbhy * (ez[0][r + 1] - ez[0][r]));
                    hy[1][r] = fHy[1][r] * (hy[1][r] + dbhy * (ez[1][r + 1] - ez[1][r]));
                }
            }
        }

        // ---- Complete polls ----
        float ezTop[2] = {0.f, 0.f}, hyTop[2] = {0.f, 0.f}, ezBot[2] = {0.f, 0.f};
        #pragma unroll
        for (int c = 0; c < 2; ++c) {
            if (needB && colE[c]) {
                while (__float_as_uint(vB[c].w) < wantG) vB[c] = ld_pkt(pB[c]);
                ezTop[c] = vB[c].x; hyTop[c] = vB[c].y;
            }
            if (needT && colE[c]) {
                while (__float_as_uint(vT[c].w) < wantG) vT[c] = ld_pkt(pT[c]);
                ezBot[c] = vT[c].x;
            }
        }

        // ---- Boundary H ----
        float hyPrev[2] = {0.f, 0.f};
        const int last = nrows - 1;
        #pragma unroll
        for (int c = 0; c < 2; ++c) {
            if (nrows == 3) hy[c][2] = fHy[c][2] * (hy[c][2] + dbhy * (ezBot[c] - ez[c][2]));
            else            hy[c][1] = fHy[c][1] * (hy[c][1] + dbhy * (ezBot[c] - ez[c][1]));
            if (bid > 0)
                hyPrev[c] = fHyHalo[c] * (hyTop[c] + dbhy * (ez[c][0] - ezTop[c]));
        }

        // ---- E + J; publish per-column packets ASAP ----
        const int sG = t & (RSLOT - 1);
        const unsigned seqG = base + (unsigned)t + 1u;

        EUPD(0, 0, hyPrev[0], (srcHere0 && r0 == SRCI));
        EUPD(1, 0, hyPrev[1], false);
        if (colE[0]) st_pkt(&g_pktT[sG][bid][c0], ez[0][0], 0.f, seqG);
        if (colE[1]) st_pkt(&g_pktT[sG][bid][c1], ez[1][0], 0.f, seqG);

        if (nrows == 3) {
            EUPD(0, 2, hy[0][1], (srcHere0 && r0 + 2 == SRCI));
            EUPD(1, 2, hy[1][1], false);
            if (colE[0]) st_pkt(&g_pktB[sG][bid][c0], ez[0][2], hy[0][2], seqG);
            if (colE[1]) st_pkt(&g_pktB[sG][bid][c1], ez[1][2], hy[1][2], seqG);
            EUPD(0, 1, hy[0][0], (srcHere0 && r0 + 1 == SRCI));
            EUPD(1, 1, hy[1][0], false);
        } else {
            EUPD(0, 1, hy[0][0], (srcHere0 && r0 + 1 == SRCI));
            EUPD(1, 1, hy[1][0], false);
            if (colE[0]) st_pkt(&g_pktB[sG][bid][c0], ez[0][1], hy[0][1], seqG);
            if (colE[1]) st_pkt(&g_pktB[sG][bid][c1], ez[1][1], hy[1][1], seqG);
        }

        // ---- Publish warp-edge Ez for next step ----
        if (lane == 0) {
            #pragma unroll
            for (int r = 0; r < NRMAX; ++r) sEdgeL[slotW][w][r] = ez[0][r];
        }
        if (lane == 31) {
            #pragma unroll
            for (int r = 0; r < NRMAX; ++r) sEdgeR[slotW][w][r] = ez[1][r];
        }

        __syncthreads();   // single barrier per step
    }
#undef EUPD

    #pragma unroll
    for (int c = 0; c < 2; ++c) {
        if (colE[c]) {
            #pragma unroll
            for (int r = 0; r < NRMAX; ++r) {
                if (r < nrows) out[(r0 + r) * TYDIM + col[c]] = ez[c][r];
            }
        }
    }

    if (k == 0) *(volatile unsigned*)&g_epoch = base + (unsigned)n;
}

extern "C" void kernel_launch(void* const* d_in, const int* in_sizes, int n_in,
                              void* d_out, int out_size) {
    const float* src    = (const float*)d_in[0];
    const float* C1a    = (const float*)d_in[1];
    const float* C2a    = (const float*)d_in[2];
    const float* Cbdxa  = (const float*)d_in[3];
    const float* Cbdya  = (const float*)d_in[4];
    const float* dbhxa  = (const float*)d_in[5];
    const float* dbhya  = (const float*)d_in[6];
    const float* Caa    = (const float*)d_in[7];
    const float* Cba    = (const float*)d_in[8];
    const float* Cca    = (const float*)d_in[9];
    const float* Cda    = (const float*)d_in[10];
    const float* Cea    = (const float*)d_in[11];
    const float* sigex  = (const float*)d_in[12];
    const float* sigey  = (const float*)d_in[13];
    const float* sighx  = (const float*)d_in[14];
    const float* sighy  = (const float*)d_in[15];
    const int*   nsp    = (n_in >= 17) ? (const int*)d_in[16] : nullptr;

    const double EPS0 = 1e-9 / 36.0 / M_PI;
    const double MU0  = 4.0 * M_PI * 1e-7;
    const double C0   = 1.0 / sqrt(MU0 * EPS0);
    const double DX = 2.5e-8, DY = 2.5e-8;
    const double DT = 0.99 / C0 / sqrt(1.0 / (DX * DX) + 1.0 / (DY * DY));
    const float kE  = (float)(DT / EPS0);
    const float kMu = (float)(DT / MU0);

    fdtd_mlor_kernel<<<NBLK, NT>>>(src, in_sizes[0],
                                   C1a, C2a, Cbdxa, Cbdya, dbhxa, dbhya,
                                   Caa, Cba, Cca, Cda, Cea,
                                   sigex, sigey, sighx, sighy,
                                   nsp, (float*)d_out, kE, kMu);
    (void)out_size;
}

// round 11
// speedup vs baseline: 2.5327x; 1.2173x over previous
#include <cuda_runtime.h>
#include <math.h>

#ifndef M_PI
#define M_PI 3.14159265358979323846
#endif

#define NBLK  148
#define NT    448
#define NWARP 14
#define TXDIM 421
#define TYDIM 421
#define NRMAX 3
#define SRCI  210
#define SRCJ  210
#define SRCBUF 256

// Flag+data packets, ring depth 2 (slot = t&1 for writes, (t+1)&1 for reads):
//  pktT: {ez_row_first, 0, _, seq} — consumed by bid-1 as ezBot
//  pktB: {ez_row_last, hy_row_last, _, seq} — consumed by bid+1 as ezTop/hyTop
__device__ float4   g_pktT[2][NBLK][NT];
__device__ float4   g_pktB[2][NBLK][NT];
__device__ unsigned g_epoch;   // monotonic across graph replays

static __device__ __forceinline__ void st_pkt(float4* p, float x, float y, unsigned seq) {
    asm volatile("st.volatile.global.v4.f32 [%0], {%1,%2,%3,%4};"
                 :: "l"(p), "f"(x), "f"(y), "f"(0.f), "f"(__uint_as_float(seq)) : "memory");
}
static __device__ __forceinline__ float4 ld_pkt(const float4* p) {
    float4 v;
    asm volatile("ld.volatile.global.v4.f32 {%0,%1,%2,%3}, [%4];"
                 : "=f"(v.x), "=f"(v.y), "=f"(v.z), "=f"(v.w) : "l"(p) : "memory");
    return v;
}

__global__ void __launch_bounds__(NT, 1)
fdtd_mlor_kernel(const float* __restrict__ src, int src_len,
                 const float* __restrict__ C1a, const float* __restrict__ C2a,
                 const float* __restrict__ Cbdxa, const float* __restrict__ Cbdya,
                 const float* __restrict__ dbhxa, const float* __restrict__ dbhya,
                 const float* __restrict__ Caa, const float* __restrict__ Cba,
                 const float* __restrict__ Cca, const float* __restrict__ Cda,
                 const float* __restrict__ Cea,
                 const float* __restrict__ sig_ex, const float* __restrict__ sig_ey,
                 const float* __restrict__ sig_hx, const float* __restrict__ sig_hy,
                 const int* __restrict__ nsp,
                 float* __restrict__ out,
                 float kE, float kMu)
{
    const int bid  = blockIdx.x;
    const int j    = threadIdx.x;
    const int w    = j >> 5;
    const int lane = j & 31;

    const float ca   = Caa[0], cb = Cba[0], cc = Cca[0], cd = Cda[0], ce = Cea[0];
    const float C1   = C1a[0], C2 = C2a[0];
    const float Cbdx = Cbdxa[0], Cbdy = Cbdya[0];
    const float dbhx = dbhxa[0], dbhy = dbhya[0];

    int n = nsp ? nsp[0] : 200;
    if (n > src_len) n = src_len;
    if (n < 0) n = 0;

    const int r0 = (bid * TXDIM) / NBLK;
    const int r1 = ((bid + 1) * TXDIM) / NBLK;
    const int nrows = r1 - r0;                 // 2 or 3
    const bool hasL = (bid > 0);
    const bool hasU = (bid < NBLK - 1);

    const bool colE = (j < TYDIM);
    const bool colH = (j < TYDIM - 1);
    const bool colM = (j >= 1 && j < TYDIM);
    const bool inJ  = (j >= 1 && j <= TYDIM - 2);

    float cEyE = 1.f, cEyMu = 1.f, cHyMu = 1.f, cHyMuM = 1.f;
    if (colE) { float s = sig_ey[j]; cEyE = expf(-s * kE); cEyMu = expf(-s * kMu); }
    if (colH) cHyMu  = expf(-sig_hy[j]     * kMu);
    if (colM) cHyMuM = expf(-sig_hy[j - 1] * kMu);

    float fDe[NRMAX], fHx[NRMAX], fHxm[NRMAX], fHy[NRMAX];
    bool  inI[NRMAX];
    #pragma unroll
    for (int r = 0; r < NRMAX; ++r) {
        fDe[r] = 0.f; fHx[r] = 0.f; fHxm[r] = 0.f; fHy[r] = 0.f; inI[r] = false;
        if (r < nrows) {
            int i = r0 + r;
            float sx  = sig_ex[i];
            float rMu = expf(-sx * kMu);
            fDe[r]  = expf(-sx * kE) * cEyE;
            fHx[r]  = rMu * cHyMu;
            fHxm[r] = rMu * cHyMuM;
            fHy[r]  = (i < TXDIM - 1) ? expf(-sig_hx[i] * kMu) * cEyMu : 0.f;
            inI[r]  = (i >= 1 && i <= TXDIM - 2);
        }
    }
    const float fHyHalo = (r0 > 0) ? expf(-sig_hx[r0 - 1] * kMu) * cEyMu : 0.f;

    // Field state — registers for the whole run
    float ez[NRMAX]   = {0.f, 0.f, 0.f};
    float eold[NRMAX] = {0.f, 0.f, 0.f};
    float jz[NRMAX]   = {0.f, 0.f, 0.f};
    float jold[NRMAX] = {0.f, 0.f, 0.f};
    float hx[NRMAX]   = {0.f, 0.f, 0.f};
    float hxm[NRMAX]  = {0.f, 0.f, 0.f};
    float hy[NRMAX]   = {0.f, 0.f, 0.f};

    // Warp-edge Ez, double-buffered; read only AFTER the barrier (never spun on).
    __shared__ float sEdgeL[2][NWARP][4];   // lane0 column of each warp
    __shared__ float sEdgeR[2][NWARP][4];   // lane31 column of each warp
    __shared__ float sSrc[SRCBUF];

    if (j < 2 * NWARP * 4) { ((float*)sEdgeL)[j] = 0.f; ((float*)sEdgeR)[j] = 0.f; }
    if (j < n && j < SRCBUF) sSrc[j] = src[j];

    const unsigned base = *(volatile unsigned*)&g_epoch;

    // Loop-invariant packet pointers (slots are compile-time per unrolled body)
    const int bidm = hasL ? bid - 1 : bid;
    const int bidp = hasU ? bid + 1 : bid;
    const float4* pBr[2] = { &g_pktB[0][bidm][j], &g_pktB[1][bidm][j] };
    const float4* pTr[2] = { &g_pktT[0][bidp][j], &g_pktT[1][bidp][j] };
    float4*       pTw[2] = { &g_pktT[0][bid][j],  &g_pktT[1][bid][j]  };
    float4*       pBw[2] = { &g_pktB[0][bid][j],  &g_pktB[1][bid][j]  };

    const bool srcBlk = (r0 <= SRCI) && (SRCI < r1) && (j == SRCJ);
    const int  srcRow = SRCI - r0;   // valid only when srcBlk

    __syncthreads();   // init visible

    // One full time step. PR/PW = packet read/write slot, ER/EW = edge read/write slot.
#define STEP_BODY(T, PR, PW, ER, EW)                                               \
    do {                                                                           \
        const unsigned want = base + (unsigned)(T);                                \
        const bool nB = ((T) > 0) && hasL && colE;                                 \
        const bool nT = ((T) > 0) && hasU && colE;                                 \
        float4 vB = make_float4(0.f, 0.f, 0.f, 0.f);                               \
        float4 vT = make_float4(0.f, 0.f, 0.f, 0.f);                               \
        if (nB) vB = ld_pkt(pBr[PR]);                                              \
        if (nT) vT = ld_pkt(pTr[PR]);                                              \
        /* j±1 exchange: shfl in-warp, shared at warp edges */                     \
        float ezp1[NRMAX], ezm1[NRMAX];                                            \
        _Pragma("unroll")                                                          \
        for (int r = 0; r < NRMAX; ++r) {                                          \
            ezp1[r] = __shfl_down_sync(0xffffffffu, ez[r], 1);                     \
            ezm1[r] = __shfl_up_sync  (0xffffffffu, ez[r], 1);                     \
        }                                                                          \
        if (lane == 31 && w < NWARP - 1) {                                         \
            ezp1[0] = sEdgeL[ER][w + 1][0];                                        \
            ezp1[1] = sEdgeL[ER][w + 1][1];                                        \
            ezp1[2] = sEdgeL[ER][w + 1][2];                                        \
        }                                                                          \
        if (lane == 0 && w > 0) {                                                  \
            ezm1[0] = sEdgeR[ER][w - 1][0];                                        \
            ezm1[1] = sEdgeR[ER][w - 1][1];                                        \
            ezm1[2] = sEdgeR[ER][w - 1][2];                                        \
        }                                                                          \
        /* local H + J/E polynomial (overlaps poll RT) */                          \
        float phi[NRMAX], jpart[NRMAX];                                            \
        _Pragma("unroll")                                                          \
        for (int r = 0; r < NRMAX; ++r) {                                          \
            if (r < nrows) {                                                       \
                if (colH) hx[r]  = fHx[r]  * (hx[r]  - dbhx * (ezp1[r] - ez[r]));  \
                if (colM) hxm[r] = fHxm[r] * (hxm[r] - dbhx * (ez[r] - ezm1[r]));  \
                if (r + 1 < nrows)                                                 \
                    hy[r] = fHy[r] * (hy[r] + dbhy * (ez[r + 1] - ez[r]));         \
                float jp = ca * jz[r] + cb * jold[r] + cd * ez[r] + ce * eold[r];  \
                jpart[r] = jp;                                                     \
                phi[r]   = jp + jz[r];                                             \
            }                                                                      \
        }                                                                          \
        /* complete polls */                                                       \
        float ezTop = 0.f, hyTop = 0.f, ezBot = 0.f;                               \
        if (nB) {                                                                  \
            while (__float_as_uint(vB.w) < want) vB = ld_pkt(pBr[PR]);             \
            ezTop = vB.x; hyTop = vB.y;                                            \
        }                                                                          \
        if (nT) {                                                                  \
            while (__float_as_uint(vT.w) < want) vT = ld_pkt(pTr[PR]);             \
            ezBot = vT.x;                                                          \
        }                                                                          \
        /* boundary H */                                                           \
        float hyPrev = 0.f;                                                        \
        if (colE) {                                                                \
            if (nrows == 3) hy[2] = fHy[2] * (hy[2] + dbhy * (ezBot - ez[2]));     \
            else            hy[1] = fHy[1] * (hy[1] + dbhy * (ezBot - ez[1]));     \
            if (hasL) hyPrev = fHyHalo * (hyTop + dbhy * (ez[0] - ezTop));         \
        }                                                                          \
        /* E + J; publish packets ASAP */                                          \
        const unsigned seqv = want + 1u;                                           \
        const float sv = srcBlk ? sSrc[(T)] : 0.f;                                 \
        if (colE) {                                                                \
            EUPD(0, hyPrev, (srcBlk && srcRow == 0));                              \
            st_pkt(pTw[PW], ez[0], 0.f, seqv);                                     \
            if (nrows == 3) {                                                      \
                EUPD(2, hy[1], (srcBlk && srcRow == 2));                           \
                st_pkt(pBw[PW], ez[2], hy[2], seqv);                               \
                EUPD(1, hy[0], (srcBlk && srcRow == 1));                           \
            } else {                                                               \
                EUPD(1, hy[0], (srcBlk && srcRow == 1));                           \
                st_pkt(pBw[PW], ez[1], hy[1], seqv);                               \
            }                                                                      \
        }                                                                          \
        /* publish warp-edge Ez (state T+1) */                                     \
        if (lane == 0) {                                                           \
            sEdgeL[EW][w][0] = ez[0];                                              \
            sEdgeL[EW][w][1] = ez[1];                                              \
            sEdgeL[EW][w][2] = ez[2];                                              \
        }                                                                          \
        if (lane == 31) {                                                          \
            sEdgeR[EW][w][0] = ez[0];                                              \
            sEdgeR[EW][w][1] = ez[1];                                              \
            sEdgeR[EW][w][2] = ez[2];                                              \
        }                                                                          \
        __syncthreads();                                                           \
    } while (0)

#define EUPD(r, hyBelow, srcadd)                                                   \
    do {                                                                           \
        float eznew_ = 0.f;                                                        \
        if (inI[(r)] && inJ) {                                                     \
            float chy_ = hy[(r)] - (hyBelow);                                      \
            float chx_ = hx[(r)] - hxm[(r)];                                       \
            eznew_ = fDe[(r)] * (C1 * ez[(r)] + Cbdx * chy_ - Cbdy * chx_          \
                                 - C2 * phi[(r)]);                                 \
            if (srcadd) eznew_ += sv;                                              \
        }                                                                          \
        jold[(r)] = jz[(r)]; jz[(r)] = jpart[(r)] + cc * eznew_;                   \
        eold[(r)] = ez[(r)]; ez[(r)] = eznew_;                                     \
    } while (0)

    // Unrolled ×2: even step -> pkt read slot1/write slot0, edge read0/write1;
    //              odd  step -> pkt read slot0/write slot1, edge read1/write0.
    int t = 0;
    for (; t + 1 < n; t += 2) {
        STEP_BODY(t,     1, 0, 0, 1);
        STEP_BODY(t + 1, 0, 1, 1, 0);
    }
    if (t < n) {
        STEP_BODY(t, 1, 0, 0, 1);
    }
#undef EUPD
#undef STEP_BODY

    #pragma unroll
    for (int r = 0; r < NRMAX; ++r) {
        if (r < nrows && colE) out[(r0 + r) * TYDIM + j] = ez[r];
    }

    // Advance epoch for the next graph replay (same value from every block)
    if (j == 0) *(volatile unsigned*)&g_epoch = base + (unsigned)n;
}

extern "C" void kernel_launch(void* const* d_in, const int* in_sizes, int n_in,
                              void* d_out, int out_size) {
    const float* src    = (const float*)d_in[0];
    const float* C1a    = (const float*)d_in[1];
    const float* C2a    = (const float*)d_in[2];
    const float* Cbdxa  = (const float*)d_in[3];
    const float* Cbdya  = (const float*)d_in[4];
    const float* dbhxa  = (const float*)d_in[5];
    const float* dbhya  = (const float*)d_in[6];
    const float* Caa    = (const float*)d_in[7];
    const float* Cba    = (const float*)d_in[8];
    const float* Cca    = (const float*)d_in[9];
    const float* Cda    = (const float*)d_in[10];
    const float* Cea    = (const float*)d_in[11];
    const float* sigex  = (const float*)d_in[12];
    const float* sigey  = (const float*)d_in[13];
    const float* sighx  = (const float*)d_in[14];
    const float* sighy  = (const float*)d_in[15];
    const int*   nsp    = (n_in >= 17) ? (const int*)d_in[16] : nullptr;

    const double EPS0 = 1e-9 / 36.0 / M_PI;
    const double MU0  = 4.0 * M_PI * 1e-7;
    const double C0   = 1.0 / sqrt(MU0 * EPS0);
    const double DX = 2.5e-8, DY = 2.5e-8;
    const double DT = 0.99 / C0 / sqrt(1.0 / (DX * DX) + 1.0 / (DY * DY));
    const float kE  = (float)(DT / EPS0);
    const float kMu = (float)(DT / MU0);

    fdtd_mlor_kernel<<<NBLK, NT>>>(src, in_sizes[0],
                                   C1a, C2a, Cbdxa, Cbdya, dbhxa, dbhya,
                                   Caa, Cba, Cca, Cda, Cea,
                                   sigex, sigey, sighx, sighy,
                                   nsp, (float*)d_out, kE, kMu);
    (void)out_size;
}